// round 13
// baseline (speedup 1.0000x reference)
#include <cuda_runtime.h>
#include <cuda_bf16.h>
#include <cuda_fp16.h>
#include <cstdint>

#define DH   128
#define BM   128
#define BN   128
#define NTH  256
#define NQ   8192
#define NKV  8192
#define NIT  (NKV / 2 / BN)   // 32 iterations per CTA

// smem offsets from 1024-aligned base
#define SM_K0   0
#define SM_K1   32768
#define SM_V0   65536
#define SM_V1   98304
#define SM_LBUF 131072
#define SM_TMEM 132096
#define SM_MBQK 132104
#define SM_MBPV 132112
#define SMEM_TOTAL (132128 + 1024)

#define SW128(x) ((x) ^ (((x) >> 3) & 0x70))

#define IDESC_QK 0x8100490u   // kind::f16, F32 acc, bf16 a/b, M=128, N=64
#define IDESC_PV 0x8100010u   // kind::f16, F32 acc, f16  a/b, M=128, N=64
#define DESC_K(addr)  (0x4000404000010000ULL | ((uint64_t)((addr) >> 4) & 0x3FFF))

#if !defined(__CUDA_ARCH__) || defined(__CUDA_ARCH_FEAT_SM103_ALL) || \
    defined(__CUDA_ARCH_FEAT_SM100_ALL) || defined(__CUDA_ARCH_SPECIFIC__) || \
    defined(__CUDA_ARCH_FAMILY_SPECIFIC__)
#define HAS_TCGEN05 1
#else
#define HAS_TCGEN05 0
#endif

__device__ float g_Onum[2][(size_t)NQ * DH];
__device__ float g_l[2][NQ];
__device__ unsigned g_cnt[NQ / BM];                 // per-qtile finish ticket
__device__ __nv_bfloat16 g_Kbf[(size_t)NKV * DH];   // K row-major bf16
__device__ __half        g_VT[(size_t)DH * NKV];    // V^T fp16 [d][kv]

// ===== prepass: blocks 0-127 V^T (64 kv each); 128-255 K convert; zero tickets ====
__global__ __launch_bounds__(256)
void prep(const float* __restrict__ K, const float* __restrict__ V)
{
    const int tid = threadIdx.x;
    if (blockIdx.x == 0 && tid < NQ / BM) g_cnt[tid] = 0;

    if (blockIdx.x < 128) {
        const int kv0 = blockIdx.x * 64;
        const int m = tid & 31;          // kv-pair lane
        const int c4g = tid >> 5;        // 0..7
        __half2* dst = (__half2*)g_VT;
        #pragma unroll
        for (int j = 0; j < 4; j++) {
            int c4 = c4g + j * 8;        // 0..31 -> d0 = c4*4
            int kv = kv0 + m * 2;
            float4 a = *(const float4*)(V + (size_t)kv * DH + c4 * 4);
            float4 b = *(const float4*)(V + (size_t)(kv + 1) * DH + c4 * 4);
            size_t base = (((size_t)c4 * 4) * NKV + kv) >> 1;  // half2 units
            dst[base]               = __floats2half2_rn(a.x, b.x);
            dst[base + NKV / 2]     = __floats2half2_rn(a.y, b.y);
            dst[base + NKV]         = __floats2half2_rn(a.z, b.z);
            dst[base + 3 * NKV / 2] = __floats2half2_rn(a.w, b.w);
        }
    } else {
        const int blk = blockIdx.x - 128;              // 128 blocks x 1024 uint4
        const float4* src = (const float4*)K;
        #pragma unroll
        for (int j = 0; j < 4; j++) {
            int i = blk * 1024 + tid + j * 256;
            float4 a = src[2 * i], b = src[2 * i + 1];
            __nv_bfloat162 p0 = __floats2bfloat162_rn(a.x, a.y);
            __nv_bfloat162 p1 = __floats2bfloat162_rn(a.z, a.w);
            __nv_bfloat162 p2 = __floats2bfloat162_rn(b.x, b.y);
            __nv_bfloat162 p3 = __floats2bfloat162_rn(b.z, b.w);
            ((uint4*)g_Kbf)[i] = make_uint4(*(uint32_t*)&p0, *(uint32_t*)&p1,
                                            *(uint32_t*)&p2, *(uint32_t*)&p3);
        }
    }
}

#if HAS_TCGEN05
__device__ __forceinline__ uint32_t s2u(const void* p) {
    uint32_t a;
    asm("{ .reg .u64 t; cvta.to.shared.u64 t, %1; cvt.u32.u64 %0, t; }" : "=r"(a) : "l"(p));
    return a;
}
__device__ __forceinline__ uint32_t elect1() {
    uint32_t p;
    asm volatile("{ .reg .pred P; elect.sync _|P, 0xFFFFFFFF; selp.b32 %0,1,0,P; }" : "=r"(p));
    return p;
}
__device__ __forceinline__ uint32_t ex2_h2(uint32_t x) {
    uint32_t y; asm("ex2.approx.f16x2 %0, %1;" : "=r"(y) : "r"(x)); return y;
}
__device__ __forceinline__ void mma_f16_ts(uint32_t d, uint32_t a, uint64_t b,
                                           uint32_t id, uint32_t en) {
    asm volatile(
        "{\n\t.reg .pred p;\n\tsetp.ne.u32 p, %5, 0;\n\t"
        "tcgen05.mma.cta_group::1.kind::f16 [%0], [%1], %2, %3, {%4, %4, %4, %4}, p;\n\t}"
        :: "r"(d), "r"(a), "l"(b), "r"(id), "r"(0u), "r"(en) : "memory");
}
__device__ __forceinline__ void tc_commit(uint32_t mbar) {
    asm volatile(
        "tcgen05.commit.cta_group::1.mbarrier::arrive::one.shared::cluster.b64 [%0];"
        :: "r"(mbar) : "memory");
}
__device__ __forceinline__ void mbar_wait(uint32_t mbar, uint32_t parity) {
    uint32_t done;
    asm volatile(
        "{\n\t.reg .pred p;\n\t"
        "mbarrier.try_wait.parity.acquire.cta.shared::cta.b64 p, [%1], %2;\n\t"
        "selp.b32 %0, 1, 0, p;\n\t}"
        : "=r"(done) : "r"(mbar), "r"(parity) : "memory");
    if (!done) {
        asm volatile(
            "{\n\t.reg .pred P1;\n\t"
            "W_%=:\n\t"
            "mbarrier.try_wait.parity.acquire.cta.shared::cta.b64 P1, [%0], %1, 0x989680;\n\t"
            "@P1 bra.uni D_%=;\n\t"
            "bra.uni W_%=;\n\t"
            "D_%=:\n\t}"
            :: "r"(mbar), "r"(parity) : "memory");
    }
}

#define LDTM32(r, a) \
    asm volatile("tcgen05.ld.sync.aligned.32x32b.x32.b32 " \
        "{%0,%1,%2,%3,%4,%5,%6,%7,%8,%9,%10,%11,%12,%13,%14,%15," \
        "%16,%17,%18,%19,%20,%21,%22,%23,%24,%25,%26,%27,%28,%29,%30,%31}, [%32];" \
        : "=r"((r)[0]),"=r"((r)[1]),"=r"((r)[2]),"=r"((r)[3]),"=r"((r)[4]),"=r"((r)[5]), \
          "=r"((r)[6]),"=r"((r)[7]),"=r"((r)[8]),"=r"((r)[9]),"=r"((r)[10]),"=r"((r)[11]), \
          "=r"((r)[12]),"=r"((r)[13]),"=r"((r)[14]),"=r"((r)[15]),"=r"((r)[16]),"=r"((r)[17]), \
          "=r"((r)[18]),"=r"((r)[19]),"=r"((r)[20]),"=r"((r)[21]),"=r"((r)[22]),"=r"((r)[23]), \
          "=r"((r)[24]),"=r"((r)[25]),"=r"((r)[26]),"=r"((r)[27]),"=r"((r)[28]),"=r"((r)[29]), \
          "=r"((r)[30]),"=r"((r)[31]) : "r"(a))

#define STTM32(a, r) \
    asm volatile("tcgen05.st.sync.aligned.32x32b.x32.b32 [%0], " \
        "{%1,%2,%3,%4,%5,%6,%7,%8,%9,%10,%11,%12,%13,%14,%15,%16," \
        "%17,%18,%19,%20,%21,%22,%23,%24,%25,%26,%27,%28,%29,%30,%31,%32};" \
        :: "r"(a), \
          "r"((r)[0]),"r"((r)[1]),"r"((r)[2]),"r"((r)[3]),"r"((r)[4]),"r"((r)[5]), \
          "r"((r)[6]),"r"((r)[7]),"r"((r)[8]),"r"((r)[9]),"r"((r)[10]),"r"((r)[11]), \
          "r"((r)[12]),"r"((r)[13]),"r"((r)[14]),"r"((r)[15]),"r"((r)[16]),"r"((r)[17]), \
          "r"((r)[18]),"r"((r)[19]),"r"((r)[20]),"r"((r)[21]),"r"((r)[22]),"r"((r)[23]), \
          "r"((r)[24]),"r"((r)[25]),"r"((r)[26]),"r"((r)[27]),"r"((r)[28]),"r"((r)[29]), \
          "r"((r)[30]),"r"((r)[31]) : "memory")

// coalesced 16-bit tile -> K-major blocked SW128 smem (2048 uint4)
__device__ __forceinline__ void load_tile16(char* smdst, const uint16_t* gsrc,
                                            size_t rowstride_elts, int tid) {
    #pragma unroll
    for (int p = 0; p < 8; p++) {
        int f = tid + p * NTH;
        int r = f >> 4, c16 = f & 15, k0 = c16 * 8;
        uint4 v = *(const uint4*)(gsrc + (size_t)r * rowstride_elts + k0);
        uint32_t off = (uint32_t)(((r >> 3) + (k0 >> 6) * 16) * 1024)
                     + SW128((uint32_t)((r & 7) * 128 + (k0 & 63) * 2));
        *(uint4*)(smdst + off) = v;
    }
}
#endif  // HAS_TCGEN05

__global__ __launch_bounds__(NTH, 1)
void attn_tc(const float* __restrict__ Q, float* __restrict__ O)
{
#if HAS_TCGEN05
    extern __shared__ char smraw[];
    const uint32_t sb_raw = s2u(smraw);
    const uint32_t sb = (sb_raw + 1023u) & ~1023u;
    char* smb = smraw + (sb - sb_raw);

    const int tid = threadIdx.x, wid = tid >> 5, lane = tid & 31;
    const int qtile = blockIdx.x >> 1, half = blockIdx.x & 1;
    const int row0 = qtile * BM;
    const int kv_begin = half * (NKV / 2);

    if (wid == 0)
        asm volatile("tcgen05.alloc.cta_group::1.sync.aligned.shared::cta.b32 [%0], %1;"
                     :: "r"(sb + SM_TMEM), "r"(512u) : "memory");
    if (tid == 0) {
        asm volatile("mbarrier.init.shared.b64 [%0], %1;"
                     :: "r"(sb + SM_MBQK), "r"(1u) : "memory");
        asm volatile("mbarrier.init.shared.b64 [%0], %1;"
                     :: "r"(sb + SM_MBPV), "r"(1u) : "memory");
    }
    __syncthreads();

    uint32_t tb;
    asm volatile("ld.shared.b32 %0, [%1];" : "=r"(tb) : "r"(sb + SM_TMEM));
    // TMEM: Q[0,64) | S0[64,192) | S1[192,320) | O[320,448) | P[448,512)
    const uint32_t T_QA = tb, T_S0 = tb + 64, T_S1 = tb + 192,
                   T_O = tb + 320, T_P = tb + 448;

    const uint32_t woff = (uint32_t)(wid & 3) << 21;
    const int colbase = (wid >> 2) * 64;
    const int r_loc = (wid & 3) * 32 + lane;

    // ---- Q -> TMEM bf16 A-operand, PRE-SCALED by (1/d_k)*log2(e) ----
    const float SCL2 = (1.0f / 128.0f) * 1.4426950408889634f;
    if (wid < 4) {
        const float4* qr = (const float4*)(Q + (size_t)(row0 + tid) * DH);
        uint32_t qa[64];
        #pragma unroll
        for (int c = 0; c < 32; c++) {
            float4 q = qr[c];
            __nv_bfloat162 a = __floats2bfloat162_rn(q.x * SCL2, q.y * SCL2);
            __nv_bfloat162 b = __floats2bfloat162_rn(q.z * SCL2, q.w * SCL2);
            qa[2 * c] = *(uint32_t*)&a;
            qa[2 * c + 1] = *(uint32_t*)&b;
        }
        STTM32(T_QA + woff, qa);
        STTM32(T_QA + 32 + woff, qa + 32);
        asm volatile("tcgen05.wait::st.sync.aligned;" ::: "memory");
    }
    asm volatile("tcgen05.fence::before_thread_sync;" ::: "memory");

    // ---- preload K(0),K(1),V(0) ; issue QK(0) -> S0 ----
    load_tile16(smb + SM_K0, (const uint16_t*)(g_Kbf + (size_t)kv_begin * DH), DH, tid);
    load_tile16(smb + SM_K1, (const uint16_t*)(g_Kbf + (size_t)(kv_begin + BN) * DH), DH, tid);
    load_tile16(smb + SM_V0, (const uint16_t*)(g_VT + kv_begin), NKV, tid);
    asm volatile("fence.proxy.async.shared::cta;" ::: "memory");
    __syncthreads();
    if (wid == 0 && elect1()) {
        asm volatile("tcgen05.fence::after_thread_sync;" ::: "memory");
        uint64_t kd = DESC_K(sb + SM_K0);
        #pragma unroll
        for (int t = 0; t < 8; t++) {
            uint32_t off = (uint32_t)((t >> 2) * 1024 + (t & 3) * 2);
            mma_f16_ts(T_S0,      T_QA + t * 8, kd + off,       IDESC_QK, t > 0);
            mma_f16_ts(T_S0 + 64, T_QA + t * 8, kd + 512 + off, IDESC_QK, t > 0);
        }
        tc_commit(sb + SM_MBQK);
    }

    float l_part = 0.f;
    uint32_t qk_par = 0, pv_par = 0;

    for (int it = 0; it < NIT; it++) {
        const int b = it & 1;
        const uint32_t T_S = b ? T_S1 : T_S0;
        const uint32_t T_Snext = b ? T_S0 : T_S1;
        const uint32_t smK_next = b ? SM_K0 : SM_K1;
        const uint32_t smK_pre  = b ? SM_K1 : SM_K0;
        const uint32_t smV_cur  = b ? SM_V1 : SM_V0;
        const uint32_t smV_next = b ? SM_V0 : SM_V1;

        // 1. wait QK(it)
        mbar_wait(sb + SM_MBQK, qk_par); qk_par ^= 1;

        // 2. issue QK(it+1)
        if (it + 1 < NIT && wid == 0 && elect1()) {
            asm volatile("tcgen05.fence::after_thread_sync;" ::: "memory");
            uint64_t kd = DESC_K(sb + smK_next);
            #pragma unroll
            for (int t = 0; t < 8; t++) {
                uint32_t off = (uint32_t)((t >> 2) * 1024 + (t & 3) * 2);
                mma_f16_ts(T_Snext,      T_QA + t * 8, kd + off,       IDESC_QK, t > 0);
                mma_f16_ts(T_Snext + 64, T_QA + t * 8, kd + 512 + off, IDESC_QK, t > 0);
            }
            tc_commit(sb + SM_MBQK);
        }

        // 3. softmax, PIPELINED: LDTM half A -> (LDTM half B in flight) -> ex2 A -> ex2 B
        asm volatile("tcgen05.fence::after_thread_sync;" ::: "memory");
        uint32_t ph[32];
        {
            uint32_t rrA[32], rrB[32];
            LDTM32(rrA, T_S + (uint32_t)colbase + woff);
            asm volatile("tcgen05.wait::ld.sync.aligned;" ::: "memory");
            LDTM32(rrB, T_S + (uint32_t)colbase + 32 + woff);
            #pragma unroll
            for (int j = 0; j < 16; j++) {
                __half2 h = __floats2half2_rn(__uint_as_float(rrA[2 * j]),
                                              __uint_as_float(rrA[2 * j + 1]));
                ph[j] = ex2_h2(*(uint32_t*)&h);
            }
            asm volatile("tcgen05.wait::ld.sync.aligned;" ::: "memory");
            #pragma unroll
            for (int j = 0; j < 16; j++) {
                __half2 h = __floats2half2_rn(__uint_as_float(rrB[2 * j]),
                                              __uint_as_float(rrB[2 * j + 1]));
                ph[16 + j] = ex2_h2(*(uint32_t*)&h);
            }
            #pragma unroll
            for (int k = 0; k < 8; k++) {
                __half2 h01 = __hadd2(*(__half2*)&ph[4 * k],     *(__half2*)&ph[4 * k + 1]);
                __half2 h23 = __hadd2(*(__half2*)&ph[4 * k + 2], *(__half2*)&ph[4 * k + 3]);
                float2 f = __half22float2(__hadd2(h01, h23));
                l_part += f.x + f.y;
            }
        }

        // 4. wait PV(it-1) — has been running during step 3
        if (it > 0) { mbar_wait(sb + SM_MBPV, pv_par); pv_par ^= 1; }

        // 5. prefetch K(it+2), V(it+1)
        if (it + 2 < NIT)
            load_tile16(smb + smK_pre,
                        (const uint16_t*)(g_Kbf + (size_t)(kv_begin + (it + 2) * BN) * DH),
                        DH, tid);
        if (it + 1 < NIT)
            load_tile16(smb + smV_next,
                        (const uint16_t*)(g_VT + kv_begin + (it + 1) * BN), NKV, tid);
        asm volatile("fence.proxy.async.shared::cta;" ::: "memory");

        // 6. store P, sync, issue PV(it)
        STTM32(T_P + ((uint32_t)colbase >> 1) + woff, ph);
        asm volatile("tcgen05.wait::st.sync.aligned;" ::: "memory");
        asm volatile("tcgen05.fence::before_thread_sync;" ::: "memory");
        __syncthreads();

        if (wid == 0 && elect1()) {
            asm volatile("tcgen05.fence::after_thread_sync;" ::: "memory");
            uint64_t vd = DESC_K(sb + smV_cur);
            #pragma unroll
            for (int c = 0; c < 2; c++) {
                uint64_t vdc = vd + (uint32_t)(c * 512);
                uint32_t dcol = T_O + c * 64;
                #pragma unroll
                for (int t = 0; t < 8; t++) {
                    uint32_t off = (uint32_t)((t >> 2) * 1024 + (t & 3) * 2);
                    mma_f16_ts(dcol, T_P + t * 8, vdc + off, IDESC_PV,
                               (uint32_t)(!(it == 0 && t == 0)));
                }
            }
            tc_commit(sb + SM_MBPV);
        }
    }

    // ---- final PV wait, epilogue ----
    mbar_wait(sb + SM_MBPV, pv_par);
    asm volatile("tcgen05.fence::after_thread_sync;" ::: "memory");

    float* lb = (float*)(smb + SM_LBUF);
    lb[(wid >> 2) * 128 + r_loc] = l_part;

    const size_t grow = (size_t)(row0 + r_loc);
    {
        uint32_t rr[64];
        LDTM32(rr,      T_O + (uint32_t)colbase + woff);
        LDTM32(rr + 32, T_O + (uint32_t)colbase + 32 + woff);
        asm volatile("tcgen05.wait::ld.sync.aligned;" ::: "memory");
        float4* dst = (float4*)(g_Onum[half] + grow * DH + colbase);
        #pragma unroll
        for (int i = 0; i < 16; i++) {
            float4 o;
            o.x = __uint_as_float(rr[4 * i + 0]);
            o.y = __uint_as_float(rr[4 * i + 1]);
            o.z = __uint_as_float(rr[4 * i + 2]);
            o.w = __uint_as_float(rr[4 * i + 3]);
            dst[i] = o;
        }
    }
    __syncthreads();
    if (wid < 4) g_l[half][row0 + r_loc] = lb[r_loc] + lb[128 + r_loc];

    // ---- in-kernel combine: second finisher of the qtile writes final O ----
    __threadfence();
    __syncthreads();
    unsigned* sflag = (unsigned*)(smb + SM_LBUF + 512);
    if (tid == 0) *sflag = atomicAdd(&g_cnt[qtile], 1u);
    __syncthreads();
    if (*sflag == 1u) {
        __threadfence();   // acquire peer's g_Onum/g_l writes
        float inv = 1.0f / (g_l[0][row0 + r_loc] + g_l[1][row0 + r_loc]);
        const float4* A = (const float4*)(g_Onum[0] + grow * DH + colbase);
        const float4* B = (const float4*)(g_Onum[1] + grow * DH + colbase);
        float4* dst = (float4*)(O + grow * DH + colbase);
        #pragma unroll
        for (int i = 0; i < 16; i++) {
            float4 a = A[i], bb = B[i];
            float4 o;
            o.x = (a.x + bb.x) * inv; o.y = (a.y + bb.y) * inv;
            o.z = (a.z + bb.z) * inv; o.w = (a.w + bb.w) * inv;
            dst[i] = o;
        }
    }

    __syncthreads();
    if (tid == 0) {
        asm volatile("mbarrier.inval.shared.b64 [%0];" :: "r"(sb + SM_MBQK) : "memory");
        asm volatile("mbarrier.inval.shared.b64 [%0];" :: "r"(sb + SM_MBPV) : "memory");
    }
    __syncthreads();
    if (wid == 0)
        asm volatile("tcgen05.dealloc.cta_group::1.sync.aligned.b32 %0, %1;"
                     :: "r"(tb), "r"(512u));
#endif  // HAS_TCGEN05
}

extern "C" void kernel_launch(void* const* d_in, const int* in_sizes, int n_in,
                              void* d_out, int out_size)
{
    const float* Q = (const float*)d_in[0];
    const float* K = (const float*)d_in[1];
    const float* V = (const float*)d_in[2];
    float* O = (float*)d_out;

    cudaFuncSetAttribute(attn_tc, cudaFuncAttributeMaxDynamicSharedMemorySize, SMEM_TOTAL);

    prep<<<256, 256>>>(K, V);
    attn_tc<<<(NQ / BM) * 2, NTH, SMEM_TOTAL>>>(Q, O);
}

// round 14
// speedup vs baseline: 1.0891x; 1.0891x over previous
#include <cuda_runtime.h>
#include <cuda_bf16.h>
#include <cuda_fp16.h>
#include <cstdint>

#define DH   128
#define BM   128
#define BN   128
#define NTH  256
#define NQ   8192
#define NKV  8192
#define NIT  (NKV / 2 / BN)   // 32 iterations per CTA

// smem offsets from 1024-aligned base
#define SM_K0   0
#define SM_K1   32768
#define SM_V0   65536
#define SM_V1   98304
#define SM_V2   131072
#define SM_LBUF 163840
#define SM_TMEM 164864
#define SM_MBQK 164872
#define SM_MBPV 164880
#define SMEM_TOTAL (164896 + 1024)

#define SW128(x) ((x) ^ (((x) >> 3) & 0x70))

#define IDESC_QK 0x8100490u   // kind::f16, F32 acc, bf16 a/b, M=128, N=64
#define IDESC_PV 0x8100010u   // kind::f16, F32 acc, f16  a/b, M=128, N=64
#define DESC_K(addr)  (0x4000404000010000ULL | ((uint64_t)((addr) >> 4) & 0x3FFF))

#if !defined(__CUDA_ARCH__) || defined(__CUDA_ARCH_FEAT_SM103_ALL) || \
    defined(__CUDA_ARCH_FEAT_SM100_ALL) || defined(__CUDA_ARCH_SPECIFIC__) || \
    defined(__CUDA_ARCH_FAMILY_SPECIFIC__)
#define HAS_TCGEN05 1
#else
#define HAS_TCGEN05 0
#endif

__device__ float g_Onum[2][(size_t)NQ * DH];
__device__ float g_l[2][NQ];
__device__ __nv_bfloat16 g_Kbf[(size_t)NKV * DH];   // K row-major bf16
__device__ __half        g_VT[(size_t)DH * NKV];    // V^T fp16 [d][kv]

// ===== prepass: blocks 0-127 V^T (64 kv each, coalesced); 128-255 K convert =====
__global__ __launch_bounds__(256)
void prep(const float* __restrict__ K, const float* __restrict__ V)
{
    const int tid = threadIdx.x;
    if (blockIdx.x < 128) {
        const int kv0 = blockIdx.x * 64;
        const int m = tid & 31;          // kv-pair lane
        const int c4g = tid >> 5;        // 0..7
        __half2* dst = (__half2*)g_VT;
        #pragma unroll
        for (int j = 0; j < 4; j++) {
            int c4 = c4g + j * 8;        // 0..31 -> d0 = c4*4
            int kv = kv0 + m * 2;
            float4 a = *(const float4*)(V + (size_t)kv * DH + c4 * 4);
            float4 b = *(const float4*)(V + (size_t)(kv + 1) * DH + c4 * 4);
            size_t base = (((size_t)c4 * 4) * NKV + kv) >> 1;  // half2 units
            dst[base]               = __floats2half2_rn(a.x, b.x);
            dst[base + NKV / 2]     = __floats2half2_rn(a.y, b.y);
            dst[base + NKV]         = __floats2half2_rn(a.z, b.z);
            dst[base + 3 * NKV / 2] = __floats2half2_rn(a.w, b.w);
        }
    } else {
        const int blk = blockIdx.x - 128;              // 128 blocks x 1024 uint4
        const float4* src = (const float4*)K;
        #pragma unroll
        for (int j = 0; j < 4; j++) {
            int i = blk * 1024 + tid + j * 256;
            float4 a = src[2 * i], b = src[2 * i + 1];
            __nv_bfloat162 p0 = __floats2bfloat162_rn(a.x, a.y);
            __nv_bfloat162 p1 = __floats2bfloat162_rn(a.z, a.w);
            __nv_bfloat162 p2 = __floats2bfloat162_rn(b.x, b.y);
            __nv_bfloat162 p3 = __floats2bfloat162_rn(b.z, b.w);
            ((uint4*)g_Kbf)[i] = make_uint4(*(uint32_t*)&p0, *(uint32_t*)&p1,
                                            *(uint32_t*)&p2, *(uint32_t*)&p3);
        }
    }
}

#if HAS_TCGEN05
__device__ __forceinline__ uint32_t s2u(const void* p) {
    uint32_t a;
    asm("{ .reg .u64 t; cvta.to.shared.u64 t, %1; cvt.u32.u64 %0, t; }" : "=r"(a) : "l"(p));
    return a;
}
__device__ __forceinline__ uint32_t elect1() {
    uint32_t p;
    asm volatile("{ .reg .pred P; elect.sync _|P, 0xFFFFFFFF; selp.b32 %0,1,0,P; }" : "=r"(p));
    return p;
}
__device__ __forceinline__ uint32_t ex2_h2(uint32_t x) {
    uint32_t y; asm("ex2.approx.f16x2 %0, %1;" : "=r"(y) : "r"(x)); return y;
}
__device__ __forceinline__ void mma_f16_ts(uint32_t d, uint32_t a, uint64_t b,
                                           uint32_t id, uint32_t en) {
    asm volatile(
        "{\n\t.reg .pred p;\n\tsetp.ne.u32 p, %5, 0;\n\t"
        "tcgen05.mma.cta_group::1.kind::f16 [%0], [%1], %2, %3, {%4, %4, %4, %4}, p;\n\t}"
        :: "r"(d), "r"(a), "l"(b), "r"(id), "r"(0u), "r"(en) : "memory");
}
__device__ __forceinline__ void tc_commit(uint32_t mbar) {
    asm volatile(
        "tcgen05.commit.cta_group::1.mbarrier::arrive::one.shared::cluster.b64 [%0];"
        :: "r"(mbar) : "memory");
}
__device__ __forceinline__ void mbar_wait(uint32_t mbar, uint32_t parity) {
    uint32_t done;
    asm volatile(
        "{\n\t.reg .pred p;\n\t"
        "mbarrier.try_wait.parity.acquire.cta.shared::cta.b64 p, [%1], %2;\n\t"
        "selp.b32 %0, 1, 0, p;\n\t}"
        : "=r"(done) : "r"(mbar), "r"(parity) : "memory");
    if (!done) {
        asm volatile(
            "{\n\t.reg .pred P1;\n\t"
            "W_%=:\n\t"
            "mbarrier.try_wait.parity.acquire.cta.shared::cta.b64 P1, [%0], %1, 0x989680;\n\t"
            "@P1 bra.uni D_%=;\n\t"
            "bra.uni W_%=;\n\t"
            "D_%=:\n\t}"
            :: "r"(mbar), "r"(parity) : "memory");
    }
}

#define LDTM32(r, a) \
    asm volatile("tcgen05.ld.sync.aligned.32x32b.x32.b32 " \
        "{%0,%1,%2,%3,%4,%5,%6,%7,%8,%9,%10,%11,%12,%13,%14,%15," \
        "%16,%17,%18,%19,%20,%21,%22,%23,%24,%25,%26,%27,%28,%29,%30,%31}, [%32];" \
        : "=r"((r)[0]),"=r"((r)[1]),"=r"((r)[2]),"=r"((r)[3]),"=r"((r)[4]),"=r"((r)[5]), \
          "=r"((r)[6]),"=r"((r)[7]),"=r"((r)[8]),"=r"((r)[9]),"=r"((r)[10]),"=r"((r)[11]), \
          "=r"((r)[12]),"=r"((r)[13]),"=r"((r)[14]),"=r"((r)[15]),"=r"((r)[16]),"=r"((r)[17]), \
          "=r"((r)[18]),"=r"((r)[19]),"=r"((r)[20]),"=r"((r)[21]),"=r"((r)[22]),"=r"((r)[23]), \
          "=r"((r)[24]),"=r"((r)[25]),"=r"((r)[26]),"=r"((r)[27]),"=r"((r)[28]),"=r"((r)[29]), \
          "=r"((r)[30]),"=r"((r)[31]) : "r"(a))

#define STTM32(a, r) \
    asm volatile("tcgen05.st.sync.aligned.32x32b.x32.b32 [%0], " \
        "{%1,%2,%3,%4,%5,%6,%7,%8,%9,%10,%11,%12,%13,%14,%15,%16," \
        "%17,%18,%19,%20,%21,%22,%23,%24,%25,%26,%27,%28,%29,%30,%31,%32};" \
        :: "r"(a), \
          "r"((r)[0]),"r"((r)[1]),"r"((r)[2]),"r"((r)[3]),"r"((r)[4]),"r"((r)[5]), \
          "r"((r)[6]),"r"((r)[7]),"r"((r)[8]),"r"((r)[9]),"r"((r)[10]),"r"((r)[11]), \
          "r"((r)[12]),"r"((r)[13]),"r"((r)[14]),"r"((r)[15]),"r"((r)[16]),"r"((r)[17]), \
          "r"((r)[18]),"r"((r)[19]),"r"((r)[20]),"r"((r)[21]),"r"((r)[22]),"r"((r)[23]), \
          "r"((r)[24]),"r"((r)[25]),"r"((r)[26]),"r"((r)[27]),"r"((r)[28]),"r"((r)[29]), \
          "r"((r)[30]),"r"((r)[31]) : "memory")

// coalesced 16-bit tile -> K-major blocked SW128 smem (2048 uint4)
__device__ __forceinline__ void load_tile16(char* smdst, const uint16_t* gsrc,
                                            size_t rowstride_elts, int tid) {
    #pragma unroll
    for (int p = 0; p < 8; p++) {
        int f = tid + p * NTH;
        int r = f >> 4, c16 = f & 15, k0 = c16 * 8;
        uint4 v = *(const uint4*)(gsrc + (size_t)r * rowstride_elts + k0);
        uint32_t off = (uint32_t)(((r >> 3) + (k0 >> 6) * 16) * 1024)
                     + SW128((uint32_t)((r & 7) * 128 + (k0 & 63) * 2));
        *(uint4*)(smdst + off) = v;
    }
}
#endif  // HAS_TCGEN05

__global__ __launch_bounds__(NTH, 1)
void attn_tc(const float* __restrict__ Q)
{
#if HAS_TCGEN05
    extern __shared__ char smraw[];
    const uint32_t sb_raw = s2u(smraw);
    const uint32_t sb = (sb_raw + 1023u) & ~1023u;
    char* smb = smraw + (sb - sb_raw);

    const int tid = threadIdx.x, wid = tid >> 5, lane = tid & 31;
    const int qtile = blockIdx.x >> 1, half = blockIdx.x & 1;
    const int row0 = qtile * BM;
    const int kv_begin = half * (NKV / 2);

    if (wid == 0)
        asm volatile("tcgen05.alloc.cta_group::1.sync.aligned.shared::cta.b32 [%0], %1;"
                     :: "r"(sb + SM_TMEM), "r"(512u) : "memory");
    if (tid == 0) {
        asm volatile("mbarrier.init.shared.b64 [%0], %1;"
                     :: "r"(sb + SM_MBQK), "r"(1u) : "memory");
        asm volatile("mbarrier.init.shared.b64 [%0], %1;"
                     :: "r"(sb + SM_MBPV), "r"(1u) : "memory");
    }
    __syncthreads();

    uint32_t tb;
    asm volatile("ld.shared.b32 %0, [%1];" : "=r"(tb) : "r"(sb + SM_TMEM));
    // TMEM: Q[0,64) | S0[64,192) | S1[192,320) | O[320,448) | P[448,512)
    const uint32_t T_QA = tb, T_S0 = tb + 64, T_S1 = tb + 192,
                   T_O = tb + 320, T_P = tb + 448;

    const uint32_t woff = (uint32_t)(wid & 3) << 21;
    const int colbase = (wid >> 2) * 64;
    const int r_loc = (wid & 3) * 32 + lane;

    // ---- Q -> TMEM bf16 A-operand, PRE-SCALED by (1/d_k)*log2(e) ----
    const float SCL2 = (1.0f / 128.0f) * 1.4426950408889634f;
    if (wid < 4) {
        const float4* qr = (const float4*)(Q + (size_t)(row0 + tid) * DH);
        uint32_t qa[64];
        #pragma unroll
        for (int c = 0; c < 32; c++) {
            float4 q = qr[c];
            __nv_bfloat162 a = __floats2bfloat162_rn(q.x * SCL2, q.y * SCL2);
            __nv_bfloat162 b = __floats2bfloat162_rn(q.z * SCL2, q.w * SCL2);
            qa[2 * c] = *(uint32_t*)&a;
            qa[2 * c + 1] = *(uint32_t*)&b;
        }
        STTM32(T_QA + woff, qa);
        STTM32(T_QA + 32 + woff, qa + 32);
        asm volatile("tcgen05.wait::st.sync.aligned;" ::: "memory");
    }
    asm volatile("tcgen05.fence::before_thread_sync;" ::: "memory");

    // ---- preload K(0),K(1),V(0) ; issue QK(0) -> S0 ----
    load_tile16(smb + SM_K0, (const uint16_t*)(g_Kbf + (size_t)kv_begin * DH), DH, tid);
    load_tile16(smb + SM_K1, (const uint16_t*)(g_Kbf + (size_t)(kv_begin + BN) * DH), DH, tid);
    load_tile16(smb + SM_V0, (const uint16_t*)(g_VT + kv_begin), NKV, tid);
    asm volatile("fence.proxy.async.shared::cta;" ::: "memory");
    __syncthreads();
    if (wid == 0 && elect1()) {
        asm volatile("tcgen05.fence::after_thread_sync;" ::: "memory");
        uint64_t kd = DESC_K(sb + SM_K0);
        #pragma unroll
        for (int t = 0; t < 8; t++) {
            uint32_t off = (uint32_t)((t >> 2) * 1024 + (t & 3) * 2);
            mma_f16_ts(T_S0,      T_QA + t * 8, kd + off,       IDESC_QK, t > 0);
            mma_f16_ts(T_S0 + 64, T_QA + t * 8, kd + 512 + off, IDESC_QK, t > 0);
        }
        tc_commit(sb + SM_MBQK);
    }

    float l_part = 0.f;
    uint32_t qk_par = 0, pv_par = 0;

    const uint32_t vslot[3] = {SM_V0, SM_V1, SM_V2};

    for (int it = 0; it < NIT; it++) {
        const int b = it & 1;
        const uint32_t T_S = b ? T_S1 : T_S0;
        const uint32_t T_Snext = b ? T_S0 : T_S1;
        const uint32_t smK_next = b ? SM_K0 : SM_K1;   // K[(it+1)&1]
        const uint32_t smK_pre  = b ? SM_K1 : SM_K0;   // slot for K(it+2)
        const uint32_t smV_cur  = vslot[it % 3];
        const uint32_t smV_next = vslot[(it + 1) % 3];

        // 1. wait QK(it) -> S[b] ready, K[b] free
        mbar_wait(sb + SM_MBQK, qk_par); qk_par ^= 1;

        // 2. issue QK(it+1): runs on tensor pipe under our loads + softmax
        if (it + 1 < NIT && wid == 0 && elect1()) {
            asm volatile("tcgen05.fence::after_thread_sync;" ::: "memory");
            uint64_t kd = DESC_K(sb + smK_next);
            #pragma unroll
            for (int t = 0; t < 8; t++) {
                uint32_t off = (uint32_t)((t >> 2) * 1024 + (t & 3) * 2);
                mma_f16_ts(T_Snext,      T_QA + t * 8, kd + off,       IDESC_QK, t > 0);
                mma_f16_ts(T_Snext + 64, T_QA + t * 8, kd + 512 + off, IDESC_QK, t > 0);
            }
            tc_commit(sb + SM_MBQK);
        }

        // 3. prefetch K(it+2), V(it+1) NOW.
        //    V[(it+1)%3] is free: PV(it-2) (which read it) was waited last iteration.
        if (it + 2 < NIT)
            load_tile16(smb + smK_pre,
                        (const uint16_t*)(g_Kbf + (size_t)(kv_begin + (it + 2) * BN) * DH),
                        DH, tid);
        if (it + 1 < NIT)
            load_tile16(smb + smV_next,
                        (const uint16_t*)(g_VT + kv_begin + (it + 1) * BN), NKV, tid);
        asm volatile("fence.proxy.async.shared::cta;" ::: "memory");

        // 4. softmax, pipelined LDTM: half A -> (half B in flight) -> ex2 A -> ex2 B
        asm volatile("tcgen05.fence::after_thread_sync;" ::: "memory");
        uint32_t ph[32];
        {
            uint32_t rrA[32], rrB[32];
            LDTM32(rrA, T_S + (uint32_t)colbase + woff);
            asm volatile("tcgen05.wait::ld.sync.aligned;" ::: "memory");
            LDTM32(rrB, T_S + (uint32_t)colbase + 32 + woff);
            #pragma unroll
            for (int j = 0; j < 16; j++) {
                __half2 h = __floats2half2_rn(__uint_as_float(rrA[2 * j]),
                                              __uint_as_float(rrA[2 * j + 1]));
                ph[j] = ex2_h2(*(uint32_t*)&h);
            }
            asm volatile("tcgen05.wait::ld.sync.aligned;" ::: "memory");
            #pragma unroll
            for (int j = 0; j < 16; j++) {
                __half2 h = __floats2half2_rn(__uint_as_float(rrB[2 * j]),
                                              __uint_as_float(rrB[2 * j + 1]));
                ph[16 + j] = ex2_h2(*(uint32_t*)&h);
            }
            #pragma unroll
            for (int k = 0; k < 8; k++) {
                __half2 h01 = __hadd2(*(__half2*)&ph[4 * k],     *(__half2*)&ph[4 * k + 1]);
                __half2 h23 = __hadd2(*(__half2*)&ph[4 * k + 2], *(__half2*)&ph[4 * k + 3]);
                float2 f = __half22float2(__hadd2(h01, h23));
                l_part += f.x + f.y;
            }
        }

        // 5. wait PV(it-1) — ran under steps 3-4 -> ~free. Frees P buffer.
        if (it > 0) { mbar_wait(sb + SM_MBPV, pv_par); pv_par ^= 1; }

        // 6. store P, sync, issue PV(it)
        STTM32(T_P + ((uint32_t)colbase >> 1) + woff, ph);
        asm volatile("tcgen05.wait::st.sync.aligned;" ::: "memory");
        asm volatile("tcgen05.fence::before_thread_sync;" ::: "memory");
        __syncthreads();   // P STTM + K/V smem stores visible to warp 0

        if (wid == 0 && elect1()) {
            asm volatile("tcgen05.fence::after_thread_sync;" ::: "memory");
            uint64_t vd = DESC_K(sb + smV_cur);
            #pragma unroll
            for (int c = 0; c < 2; c++) {
                uint64_t vdc = vd + (uint32_t)(c * 512);
                uint32_t dcol = T_O + c * 64;
                #pragma unroll
                for (int t = 0; t < 8; t++) {
                    uint32_t off = (uint32_t)((t >> 2) * 1024 + (t & 3) * 2);
                    mma_f16_ts(dcol, T_P + t * 8, vdc + off, IDESC_PV,
                               (uint32_t)(!(it == 0 && t == 0)));
                }
            }
            tc_commit(sb + SM_MBPV);
        }
    }

    // ---- final PV wait, epilogue ----
    mbar_wait(sb + SM_MBPV, pv_par);
    asm volatile("tcgen05.fence::after_thread_sync;" ::: "memory");

    float* lb = (float*)(smb + SM_LBUF);
    lb[(wid >> 2) * 128 + r_loc] = l_part;

    const size_t grow = (size_t)(row0 + r_loc);
    {
        uint32_t rr[64];
        LDTM32(rr,      T_O + (uint32_t)colbase + woff);
        LDTM32(rr + 32, T_O + (uint32_t)colbase + 32 + woff);
        asm volatile("tcgen05.wait::ld.sync.aligned;" ::: "memory");
        float4* dst = (float4*)(g_Onum[half] + grow * DH + colbase);
        #pragma unroll
        for (int i = 0; i < 16; i++) {
            float4 o;
            o.x = __uint_as_float(rr[4 * i + 0]);
            o.y = __uint_as_float(rr[4 * i + 1]);
            o.z = __uint_as_float(rr[4 * i + 2]);
            o.w = __uint_as_float(rr[4 * i + 3]);
            dst[i] = o;
        }
    }
    __syncthreads();
    if (wid < 4) g_l[half][row0 + r_loc] = lb[r_loc] + lb[128 + r_loc];

    __syncthreads();
    if (tid == 0) {
        asm volatile("mbarrier.inval.shared.b64 [%0];" :: "r"(sb + SM_MBQK) : "memory");
        asm volatile("mbarrier.inval.shared.b64 [%0];" :: "r"(sb + SM_MBPV) : "memory");
    }
    __syncthreads();
    if (wid == 0)
        asm volatile("tcgen05.dealloc.cta_group::1.sync.aligned.b32 %0, %1;"
                     :: "r"(tb), "r"(512u));
#endif  // HAS_TCGEN05
}

__global__ __launch_bounds__(256)
void combine_k(float* __restrict__ O)
{
    int base = (blockIdx.x * 256 + threadIdx.x) * 4;
    if (base >= NQ * DH / 4) return;
    int row = base >> 5;
    float inv = 1.0f / (g_l[0][row] + g_l[1][row]);
    const float4* A = (const float4*)g_Onum[0];
    const float4* B = (const float4*)g_Onum[1];
    float4* Og = (float4*)O;
    #pragma unroll
    for (int k = 0; k < 4; k++) {
        float4 a = A[base + k], b = B[base + k];
        float4 o;
        o.x = (a.x + b.x) * inv; o.y = (a.y + b.y) * inv;
        o.z = (a.z + b.z) * inv; o.w = (a.w + b.w) * inv;
        Og[base + k] = o;
    }
}

extern "C" void kernel_launch(void* const* d_in, const int* in_sizes, int n_in,
                              void* d_out, int out_size)
{
    const float* Q = (const float*)d_in[0];
    const float* K = (const float*)d_in[1];
    const float* V = (const float*)d_in[2];
    float* O = (float*)d_out;

    cudaFuncSetAttribute(attn_tc, cudaFuncAttributeMaxDynamicSharedMemorySize, SMEM_TOTAL);

    prep<<<256, 256>>>(K, V);
    attn_tc<<<(NQ / BM) * 2, NTH, SMEM_TOTAL>>>(Q);
    combine_k<<<NQ * DH / 16 / 256, 256>>>(O);
}

// round 15
// speedup vs baseline: 1.0896x; 1.0004x over previous
#include <cuda_runtime.h>
#include <cuda_bf16.h>
#include <cuda_fp16.h>
#include <cstdint>

#define DH   128
#define BM   128
#define BN   128
#define NTH  256
#define NQ   8192
#define NKV  8192
#define NIT  (NKV / 2 / BN)   // 32 iterations per CTA

// smem offsets from 1024-aligned base
#define SM_K0   0
#define SM_K1   32768
#define SM_V0   65536
#define SM_V1   98304
#define SM_V2   131072
#define SM_LBUF 163840
#define SM_TMEM 164864
#define SM_MBQK 164872
#define SM_MBPV 164880
#define SMEM_TOTAL (164896 + 1024)

#define SW128(x) ((x) ^ (((x) >> 3) & 0x70))

#define IDESC_QK 0x8100490u   // kind::f16, F32 acc, bf16 a/b, M=128, N=64
#define IDESC_PV 0x8100010u   // kind::f16, F32 acc, f16  a/b, M=128, N=64
#define DESC_K(addr)  (0x4000404000010000ULL | ((uint64_t)((addr) >> 4) & 0x3FFF))

#if !defined(__CUDA_ARCH__) || defined(__CUDA_ARCH_FEAT_SM103_ALL) || \
    defined(__CUDA_ARCH_FEAT_SM100_ALL) || defined(__CUDA_ARCH_SPECIFIC__) || \
    defined(__CUDA_ARCH_FAMILY_SPECIFIC__)
#define HAS_TCGEN05 1
#else
#define HAS_TCGEN05 0
#endif

__device__ float g_Onum[2][(size_t)NQ * DH];
__device__ float g_l[2][NQ];
__device__ __nv_bfloat16 g_Kbf[(size_t)NKV * DH];   // K row-major bf16
__device__ __half        g_VT[(size_t)DH * NKV];    // V^T fp16 [d][kv]

// ===== prepass: blocks 0-127 V^T (64 kv each, coalesced); 128-255 K convert =====
__global__ __launch_bounds__(256)
void prep(const float* __restrict__ K, const float* __restrict__ V)
{
    const int tid = threadIdx.x;
    if (blockIdx.x < 128) {
        const int kv0 = blockIdx.x * 64;
        const int m = tid & 31;          // kv-pair lane
        const int c4g = tid >> 5;        // 0..7
        __half2* dst = (__half2*)g_VT;
        #pragma unroll
        for (int j = 0; j < 4; j++) {
            int c4 = c4g + j * 8;        // 0..31 -> d0 = c4*4
            int kv = kv0 + m * 2;
            float4 a = *(const float4*)(V + (size_t)kv * DH + c4 * 4);
            float4 b = *(const float4*)(V + (size_t)(kv + 1) * DH + c4 * 4);
            size_t base = (((size_t)c4 * 4) * NKV + kv) >> 1;  // half2 units
            dst[base]               = __floats2half2_rn(a.x, b.x);
            dst[base + NKV / 2]     = __floats2half2_rn(a.y, b.y);
            dst[base + NKV]         = __floats2half2_rn(a.z, b.z);
            dst[base + 3 * NKV / 2] = __floats2half2_rn(a.w, b.w);
        }
    } else {
        const int blk = blockIdx.x - 128;              // 128 blocks x 1024 uint4
        const float4* src = (const float4*)K;
        #pragma unroll
        for (int j = 0; j < 4; j++) {
            int i = blk * 1024 + tid + j * 256;
            float4 a = src[2 * i], b = src[2 * i + 1];
            __nv_bfloat162 p0 = __floats2bfloat162_rn(a.x, a.y);
            __nv_bfloat162 p1 = __floats2bfloat162_rn(a.z, a.w);
            __nv_bfloat162 p2 = __floats2bfloat162_rn(b.x, b.y);
            __nv_bfloat162 p3 = __floats2bfloat162_rn(b.z, b.w);
            ((uint4*)g_Kbf)[i] = make_uint4(*(uint32_t*)&p0, *(uint32_t*)&p1,
                                            *(uint32_t*)&p2, *(uint32_t*)&p3);
        }
    }
}

#if HAS_TCGEN05
__device__ __forceinline__ uint32_t s2u(const void* p) {
    uint32_t a;
    asm("{ .reg .u64 t; cvta.to.shared.u64 t, %1; cvt.u32.u64 %0, t; }" : "=r"(a) : "l"(p));
    return a;
}
__device__ __forceinline__ uint32_t elect1() {
    uint32_t p;
    asm volatile("{ .reg .pred P; elect.sync _|P, 0xFFFFFFFF; selp.b32 %0,1,0,P; }" : "=r"(p));
    return p;
}
__device__ __forceinline__ uint32_t ex2_h2(uint32_t x) {
    uint32_t y; asm("ex2.approx.f16x2 %0, %1;" : "=r"(y) : "r"(x)); return y;
}
__device__ __forceinline__ void mma_f16_ts(uint32_t d, uint32_t a, uint64_t b,
                                           uint32_t id, uint32_t en) {
    asm volatile(
        "{\n\t.reg .pred p;\n\tsetp.ne.u32 p, %5, 0;\n\t"
        "tcgen05.mma.cta_group::1.kind::f16 [%0], [%1], %2, %3, {%4, %4, %4, %4}, p;\n\t}"
        :: "r"(d), "r"(a), "l"(b), "r"(id), "r"(0u), "r"(en) : "memory");
}
__device__ __forceinline__ void tc_commit(uint32_t mbar) {
    asm volatile(
        "tcgen05.commit.cta_group::1.mbarrier::arrive::one.shared::cluster.b64 [%0];"
        :: "r"(mbar) : "memory");
}
__device__ __forceinline__ void mbar_wait(uint32_t mbar, uint32_t parity) {
    uint32_t done;
    asm volatile(
        "{\n\t.reg .pred p;\n\t"
        "mbarrier.try_wait.parity.acquire.cta.shared::cta.b64 p, [%1], %2;\n\t"
        "selp.b32 %0, 1, 0, p;\n\t}"
        : "=r"(done) : "r"(mbar), "r"(parity) : "memory");
    if (!done) {
        asm volatile(
            "{\n\t.reg .pred P1;\n\t"
            "W_%=:\n\t"
            "mbarrier.try_wait.parity.acquire.cta.shared::cta.b64 P1, [%0], %1, 0x989680;\n\t"
            "@P1 bra.uni D_%=;\n\t"
            "bra.uni W_%=;\n\t"
            "D_%=:\n\t}"
            :: "r"(mbar), "r"(parity) : "memory");
    }
}

#define LDTM32(r, a) \
    asm volatile("tcgen05.ld.sync.aligned.32x32b.x32.b32 " \
        "{%0,%1,%2,%3,%4,%5,%6,%7,%8,%9,%10,%11,%12,%13,%14,%15," \
        "%16,%17,%18,%19,%20,%21,%22,%23,%24,%25,%26,%27,%28,%29,%30,%31}, [%32];" \
        : "=r"((r)[0]),"=r"((r)[1]),"=r"((r)[2]),"=r"((r)[3]),"=r"((r)[4]),"=r"((r)[5]), \
          "=r"((r)[6]),"=r"((r)[7]),"=r"((r)[8]),"=r"((r)[9]),"=r"((r)[10]),"=r"((r)[11]), \
          "=r"((r)[12]),"=r"((r)[13]),"=r"((r)[14]),"=r"((r)[15]),"=r"((r)[16]),"=r"((r)[17]), \
          "=r"((r)[18]),"=r"((r)[19]),"=r"((r)[20]),"=r"((r)[21]),"=r"((r)[22]),"=r"((r)[23]), \
          "=r"((r)[24]),"=r"((r)[25]),"=r"((r)[26]),"=r"((r)[27]),"=r"((r)[28]),"=r"((r)[29]), \
          "=r"((r)[30]),"=r"((r)[31]) : "r"(a))

#define STTM32(a, r) \
    asm volatile("tcgen05.st.sync.aligned.32x32b.x32.b32 [%0], " \
        "{%1,%2,%3,%4,%5,%6,%7,%8,%9,%10,%11,%12,%13,%14,%15,%16," \
        "%17,%18,%19,%20,%21,%22,%23,%24,%25,%26,%27,%28,%29,%30,%31,%32};" \
        :: "r"(a), \
          "r"((r)[0]),"r"((r)[1]),"r"((r)[2]),"r"((r)[3]),"r"((r)[4]),"r"((r)[5]), \
          "r"((r)[6]),"r"((r)[7]),"r"((r)[8]),"r"((r)[9]),"r"((r)[10]),"r"((r)[11]), \
          "r"((r)[12]),"r"((r)[13]),"r"((r)[14]),"r"((r)[15]),"r"((r)[16]),"r"((r)[17]), \
          "r"((r)[18]),"r"((r)[19]),"r"((r)[20]),"r"((r)[21]),"r"((r)[22]),"r"((r)[23]), \
          "r"((r)[24]),"r"((r)[25]),"r"((r)[26]),"r"((r)[27]),"r"((r)[28]),"r"((r)[29]), \
          "r"((r)[30]),"r"((r)[31]) : "memory")

// coalesced 16-bit tile -> K-major blocked SW128 smem (2048 uint4)
__device__ __forceinline__ void load_tile16(char* smdst, const uint16_t* gsrc,
                                            size_t rowstride_elts, int tid) {
    #pragma unroll
    for (int p = 0; p < 8; p++) {
        int f = tid + p * NTH;
        int r = f >> 4, c16 = f & 15, k0 = c16 * 8;
        uint4 v = *(const uint4*)(gsrc + (size_t)r * rowstride_elts + k0);
        uint32_t off = (uint32_t)(((r >> 3) + (k0 >> 6) * 16) * 1024)
                     + SW128((uint32_t)((r & 7) * 128 + (k0 & 63) * 2));
        *(uint4*)(smdst + off) = v;
    }
}
#endif  // HAS_TCGEN05

__global__ __launch_bounds__(NTH, 1)
void attn_tc(const float* __restrict__ Q)
{
#if HAS_TCGEN05
    extern __shared__ char smraw[];
    const uint32_t sb_raw = s2u(smraw);
    const uint32_t sb = (sb_raw + 1023u) & ~1023u;
    char* smb = smraw + (sb - sb_raw);

    const int tid = threadIdx.x, wid = tid >> 5, lane = tid & 31;
    const int qtile = blockIdx.x >> 1, half = blockIdx.x & 1;
    const int row0 = qtile * BM;
    const int kv_begin = half * (NKV / 2);

    if (wid == 0)
        asm volatile("tcgen05.alloc.cta_group::1.sync.aligned.shared::cta.b32 [%0], %1;"
                     :: "r"(sb + SM_TMEM), "r"(512u) : "memory");
    if (tid == 0) {
        asm volatile("mbarrier.init.shared.b64 [%0], %1;"
                     :: "r"(sb + SM_MBQK), "r"(1u) : "memory");
        asm volatile("mbarrier.init.shared.b64 [%0], %1;"
                     :: "r"(sb + SM_MBPV), "r"(1u) : "memory");
    }
    __syncthreads();

    uint32_t tb;
    asm volatile("ld.shared.b32 %0, [%1];" : "=r"(tb) : "r"(sb + SM_TMEM));
    // TMEM: Q[0,64) | S0[64,192) | S1[192,320) | O[320,448) | P[448,512)
    const uint32_t T_QA = tb, T_S0 = tb + 64, T_S1 = tb + 192,
                   T_O = tb + 320, T_P = tb + 448;

    const uint32_t woff = (uint32_t)(wid & 3) << 21;
    const int colbase = (wid >> 2) * 64;
    const int r_loc = (wid & 3) * 32 + lane;

    // ---- Q -> TMEM bf16 A-operand, PRE-SCALED by (1/d_k)*log2(e) ----
    const float SCL2 = (1.0f / 128.0f) * 1.4426950408889634f;
    if (wid < 4) {
        const float4* qr = (const float4*)(Q + (size_t)(row0 + tid) * DH);
        uint32_t qa[64];
        #pragma unroll
        for (int c = 0; c < 32; c++) {
            float4 q = qr[c];
            __nv_bfloat162 a = __floats2bfloat162_rn(q.x * SCL2, q.y * SCL2);
            __nv_bfloat162 b = __floats2bfloat162_rn(q.z * SCL2, q.w * SCL2);
            qa[2 * c] = *(uint32_t*)&a;
            qa[2 * c + 1] = *(uint32_t*)&b;
        }
        STTM32(T_QA + woff, qa);
        STTM32(T_QA + 32 + woff, qa + 32);
        asm volatile("tcgen05.wait::st.sync.aligned;" ::: "memory");
    }
    asm volatile("tcgen05.fence::before_thread_sync;" ::: "memory");

    // ---- preload K(0),K(1),V(0) ; issue QK(0) -> S0 ----
    load_tile16(smb + SM_K0, (const uint16_t*)(g_Kbf + (size_t)kv_begin * DH), DH, tid);
    load_tile16(smb + SM_K1, (const uint16_t*)(g_Kbf + (size_t)(kv_begin + BN) * DH), DH, tid);
    load_tile16(smb + SM_V0, (const uint16_t*)(g_VT + kv_begin), NKV, tid);
    asm volatile("fence.proxy.async.shared::cta;" ::: "memory");
    __syncthreads();
    if (wid == 0 && elect1()) {
        asm volatile("tcgen05.fence::after_thread_sync;" ::: "memory");
        uint64_t kd = DESC_K(sb + SM_K0);
        #pragma unroll
        for (int t = 0; t < 8; t++) {
            uint32_t off = (uint32_t)((t >> 2) * 1024 + (t & 3) * 2);
            mma_f16_ts(T_S0,      T_QA + t * 8, kd + off,       IDESC_QK, t > 0);
            mma_f16_ts(T_S0 + 64, T_QA + t * 8, kd + 512 + off, IDESC_QK, t > 0);
        }
        tc_commit(sb + SM_MBQK);
    }

    float l_part = 0.f;
    uint32_t qk_par = 0, pv_par = 0;

    const uint32_t vslot[3] = {SM_V0, SM_V1, SM_V2};

    for (int it = 0; it < NIT; it++) {
        const int b = it & 1;
        const uint32_t T_S = b ? T_S1 : T_S0;
        const uint32_t T_Snext = b ? T_S0 : T_S1;
        const uint32_t smK_next = b ? SM_K0 : SM_K1;   // K[(it+1)&1]
        const uint32_t smK_pre  = b ? SM_K1 : SM_K0;   // slot for K(it+2)
        const uint32_t smV_cur  = vslot[it % 3];
        const uint32_t smV_next = vslot[(it + 1) % 3];

        // 1. wait QK(it) -> S[b] ready, K[b] free
        mbar_wait(sb + SM_MBQK, qk_par); qk_par ^= 1;

        // 2. issue QK(it+1): runs on tensor pipe under our loads + softmax
        if (it + 1 < NIT && wid == 0 && elect1()) {
            asm volatile("tcgen05.fence::after_thread_sync;" ::: "memory");
            uint64_t kd = DESC_K(sb + smK_next);
            #pragma unroll
            for (int t = 0; t < 8; t++) {
                uint32_t off = (uint32_t)((t >> 2) * 1024 + (t & 3) * 2);
                mma_f16_ts(T_Snext,      T_QA + t * 8, kd + off,       IDESC_QK, t > 0);
                mma_f16_ts(T_Snext + 64, T_QA + t * 8, kd + 512 + off, IDESC_QK, t > 0);
            }
            tc_commit(sb + SM_MBQK);
        }

        // 3. prefetch K(it+2), V(it+1) NOW.
        //    V[(it+1)%3] is free: PV(it-2) (which read it) was waited last iteration.
        if (it + 2 < NIT)
            load_tile16(smb + smK_pre,
                        (const uint16_t*)(g_Kbf + (size_t)(kv_begin + (it + 2) * BN) * DH),
                        DH, tid);
        if (it + 1 < NIT)
            load_tile16(smb + smV_next,
                        (const uint16_t*)(g_VT + kv_begin + (it + 1) * BN), NKV, tid);
        asm volatile("fence.proxy.async.shared::cta;" ::: "memory");

        // 4. softmax, pipelined LDTM: half A -> (half B in flight) -> ex2 A -> ex2 B
        asm volatile("tcgen05.fence::after_thread_sync;" ::: "memory");
        uint32_t ph[32];
        {
            uint32_t rrA[32], rrB[32];
            LDTM32(rrA, T_S + (uint32_t)colbase + woff);
            asm volatile("tcgen05.wait::ld.sync.aligned;" ::: "memory");
            LDTM32(rrB, T_S + (uint32_t)colbase + 32 + woff);
            #pragma unroll
            for (int j = 0; j < 16; j++) {
                __half2 h = __floats2half2_rn(__uint_as_float(rrA[2 * j]),
                                              __uint_as_float(rrA[2 * j + 1]));
                ph[j] = ex2_h2(*(uint32_t*)&h);
            }
            asm volatile("tcgen05.wait::ld.sync.aligned;" ::: "memory");
            #pragma unroll
            for (int j = 0; j < 16; j++) {
                __half2 h = __floats2half2_rn(__uint_as_float(rrB[2 * j]),
                                              __uint_as_float(rrB[2 * j + 1]));
                ph[16 + j] = ex2_h2(*(uint32_t*)&h);
            }
            #pragma unroll
            for (int k = 0; k < 8; k++) {
                __half2 h01 = __hadd2(*(__half2*)&ph[4 * k],     *(__half2*)&ph[4 * k + 1]);
                __half2 h23 = __hadd2(*(__half2*)&ph[4 * k + 2], *(__half2*)&ph[4 * k + 3]);
                float2 f = __half22float2(__hadd2(h01, h23));
                l_part += f.x + f.y;
            }
        }

        // 5. wait PV(it-1) — ran under steps 3-4 -> ~free. Frees P buffer.
        if (it > 0) { mbar_wait(sb + SM_MBPV, pv_par); pv_par ^= 1; }

        // 6. store P, sync, issue PV(it)
        STTM32(T_P + ((uint32_t)colbase >> 1) + woff, ph);
        asm volatile("tcgen05.wait::st.sync.aligned;" ::: "memory");
        asm volatile("tcgen05.fence::before_thread_sync;" ::: "memory");
        __syncthreads();   // P STTM + K/V smem stores visible to warp 0

        if (wid == 0 && elect1()) {
            asm volatile("tcgen05.fence::after_thread_sync;" ::: "memory");
            uint64_t vd = DESC_K(sb + smV_cur);
            #pragma unroll
            for (int c = 0; c < 2; c++) {
                uint64_t vdc = vd + (uint32_t)(c * 512);
                uint32_t dcol = T_O + c * 64;
                #pragma unroll
                for (int t = 0; t < 8; t++) {
                    uint32_t off = (uint32_t)((t >> 2) * 1024 + (t & 3) * 2);
                    mma_f16_ts(dcol, T_P + t * 8, vdc + off, IDESC_PV,
                               (uint32_t)(!(it == 0 && t == 0)));
                }
            }
            tc_commit(sb + SM_MBPV);
        }
    }

    // ---- final PV wait, epilogue ----
    mbar_wait(sb + SM_MBPV, pv_par);
    asm volatile("tcgen05.fence::after_thread_sync;" ::: "memory");

    float* lb = (float*)(smb + SM_LBUF);
    lb[(wid >> 2) * 128 + r_loc] = l_part;

    const size_t grow = (size_t)(row0 + r_loc);
    {
        uint32_t rr[64];
        LDTM32(rr,      T_O + (uint32_t)colbase + woff);
        LDTM32(rr + 32, T_O + (uint32_t)colbase + 32 + woff);
        asm volatile("tcgen05.wait::ld.sync.aligned;" ::: "memory");
        float4* dst = (float4*)(g_Onum[half] + grow * DH + colbase);
        #pragma unroll
        for (int i = 0; i < 16; i++) {
            float4 o;
            o.x = __uint_as_float(rr[4 * i + 0]);
            o.y = __uint_as_float(rr[4 * i + 1]);
            o.z = __uint_as_float(rr[4 * i + 2]);
            o.w = __uint_as_float(rr[4 * i + 3]);
            dst[i] = o;
        }
    }
    __syncthreads();
    if (wid < 4) g_l[half][row0 + r_loc] = lb[r_loc] + lb[128 + r_loc];

    __syncthreads();
    if (tid == 0) {
        asm volatile("mbarrier.inval.shared.b64 [%0];" :: "r"(sb + SM_MBQK) : "memory");
        asm volatile("mbarrier.inval.shared.b64 [%0];" :: "r"(sb + SM_MBPV) : "memory");
    }
    __syncthreads();
    if (wid == 0)
        asm volatile("tcgen05.dealloc.cta_group::1.sync.aligned.b32 %0, %1;"
                     :: "r"(tb), "r"(512u));
#endif  // HAS_TCGEN05
}

__global__ __launch_bounds__(256)
void combine_k(float* __restrict__ O)
{
    int base = (blockIdx.x * 256 + threadIdx.x) * 4;
    if (base >= NQ * DH / 4) return;
    int row = base >> 5;
    float inv = 1.0f / (g_l[0][row] + g_l[1][row]);
    const float4* A = (const float4*)g_Onum[0];
    const float4* B = (const float4*)g_Onum[1];
    float4* Og = (float4*)O;
    #pragma unroll
    for (int k = 0; k < 4; k++) {
        float4 a = A[base + k], b = B[base + k];
        float4 o;
        o.x = (a.x + b.x) * inv; o.y = (a.y + b.y) * inv;
        o.z = (a.z + b.z) * inv; o.w = (a.w + b.w) * inv;
        Og[base + k] = o;
    }
}

extern "C" void kernel_launch(void* const* d_in, const int* in_sizes, int n_in,
                              void* d_out, int out_size)
{
    const float* Q = (const float*)d_in[0];
    const float* K = (const float*)d_in[1];
    const float* V = (const float*)d_in[2];
    float* O = (float*)d_out;

    cudaFuncSetAttribute(attn_tc, cudaFuncAttributeMaxDynamicSharedMemorySize, SMEM_TOTAL);

    prep<<<256, 256>>>(K, V);
    attn_tc<<<(NQ / BM) * 2, NTH, SMEM_TOTAL>>>(Q);
    combine_k<<<NQ * DH / 16 / 256, 256>>>(O);
}